// round 15
// baseline (speedup 1.0000x reference)
#include <cuda_runtime.h>
#include <cuda_fp16.h>
#include <cstdint>

#define BB    4
#define CC    128
#define HEADS 4
#define DH    32
#define HW    4096
#define MEMN  16
#define NTOT  4112   // HW + MEM
#define NPAD  4224   // 33*128, zero-padded tail
#define NBH   (BB * HEADS)

#define SCALEF 0.2550889456012103f  // rsqrt(32) * log2(e)

// scratch
__device__ __half g_xT[(size_t)BB * NPAD * CC];    // fp16 [b][n][c]
__device__ __half g_wqh[384 * CC];                 // fp16 w_qkv [o][c]
__device__ __half g_woh[CC * CC];                  // fp16 w_out [o][c]
__device__ __half g_Qh[(size_t)NBH * NPAD * DH];   // fp16 [bh][n][d], pre-scaled
__device__ __half g_K[(size_t)NBH * NPAD * DH];    // fp16 [bh][n][d]
__device__ __half g_VT[(size_t)NBH * DH * NPAD];   // fp16 [bh][d][n]
__device__ __half g_OT[(size_t)BB * HW * CC];      // fp16 [b][n][hid]

__device__ __forceinline__ uint32_t pk2(float lo, float hi) {
    __half2 h = __floats2half2_rn(lo, hi);
    return *(uint32_t*)&h;
}
__device__ __forceinline__ void mma_f16(float& d0, float& d1, float& d2, float& d3,
                                        uint32_t a0, uint32_t a1, uint32_t a2, uint32_t a3,
                                        uint32_t b0, uint32_t b1) {
    asm volatile("mma.sync.aligned.m16n8k16.row.col.f32.f16.f16.f32 "
                 "{%0,%1,%2,%3},{%4,%5,%6,%7},{%8,%9},{%0,%1,%2,%3};"
                 : "+f"(d0), "+f"(d1), "+f"(d2), "+f"(d3)
                 : "r"(a0), "r"(a1), "r"(a2), "r"(a3), "r"(b0), "r"(b1));
}
__device__ __forceinline__ void mma_f16acc(uint32_t& d0, uint32_t& d1,
                                           uint32_t a0, uint32_t a1, uint32_t a2, uint32_t a3,
                                           uint32_t b0, uint32_t b1) {
    asm volatile("mma.sync.aligned.m16n8k16.row.col.f16.f16.f16.f16 "
                 "{%0,%1},{%2,%3,%4,%5},{%6,%7},{%0,%1};"
                 : "+r"(d0), "+r"(d1)
                 : "r"(a0), "r"(a1), "r"(a2), "r"(a3), "r"(b0), "r"(b1));
}
__device__ __forceinline__ void cp16(uint32_t dst, const void* src) {
    asm volatile("cp.async.cg.shared.global [%0], [%1], 16;" :: "r"(dst), "l"(src));
}
__device__ __forceinline__ uint32_t h2exp2(uint32_t v) {
    uint32_t r;
    asm("ex2.approx.f16x2 %0, %1;" : "=r"(r) : "r"(v));
    return r;
}

// ---------------------------------------------------------------------------
// Kernel 0: prep — weights->fp16 + x_ext->fp16 transposed, one launch.
// ---------------------------------------------------------------------------
__global__ __launch_bounds__(256) void prep(const float* __restrict__ x,
                                            const float* __restrict__ memv,
                                            const float* __restrict__ wq,
                                            const float* __restrict__ wo) {
    __shared__ __half s[64 * 136];
    const int tid = threadIdx.x;
    if (blockIdx.x < 264) {
        const int b = blockIdx.x / 66, n0 = (blockIdx.x % 66) * 64;
        for (int u = tid; u < 64 * CC; u += 256) {
            const int ci = u >> 6, nj = u & 63;
            const int n = n0 + nj;
            float v = 0.f;
            if (n < HW)        v = x[((size_t)b * CC + ci) * HW + n];
            else if (n < NTOT) v = memv[ci * MEMN + (n - HW)];
            s[nj * 136 + ci] = __float2half(v);
        }
        __syncthreads();
        for (int u = tid; u < 64 * 64; u += 256) {
            const int nj = u >> 6, w = u & 63;
            const int n = n0 + nj;
            if (n < NTOT)
                ((uint32_t*)&g_xT[(size_t)(b * NPAD + n) * CC])[w] = *(uint32_t*)&s[nj * 136 + w * 2];
        }
    } else {
        const int i = (blockIdx.x - 264) * 256 + tid;
        if (i < 384 * CC) g_wqh[i] = __float2half(wq[i]);
        if (i < CC * CC)  g_woh[i] = __float2half(wo[i]);
    }
}

// ---------------------------------------------------------------------------
// Kernel 1: qkv tensor-core GEMM. C[o][n] = sum_c w[o][c] * xT[n][c].
// ---------------------------------------------------------------------------
__global__ __launch_bounds__(256) void qkv_tc() {
    __shared__ __align__(16) __half sA[128 * 72];
    __shared__ __align__(16) __half sB[128 * 72];
    const int b  = blockIdx.z;
    const int o0 = blockIdx.y * 128;
    const int n0 = blockIdx.x * 128;
    const int tid = threadIdx.x;
    const int warp = tid >> 5, lane = tid & 31;
    const int wm = warp >> 1, wn = warp & 1;
    const int g = lane >> 2, t = lane & 3;

    const uint32_t aBase = (uint32_t)__cvta_generic_to_shared(sA);
    const uint32_t bBase = (uint32_t)__cvta_generic_to_shared(sB);
    const uint32_t* A32 = (const uint32_t*)sA;
    const uint32_t* B32 = (const uint32_t*)sB;

    float C[2][8][4];
#pragma unroll
    for (int mi = 0; mi < 2; ++mi)
#pragma unroll
        for (int nj = 0; nj < 8; ++nj)
            C[mi][nj][0] = C[mi][nj][1] = C[mi][nj][2] = C[mi][nj][3] = 0.f;

    for (int kc = 0; kc < 2; ++kc) {
        const int k0 = kc * 64;
        for (int u = tid; u < 1024; u += 256) {
            const int row = u >> 3, c = u & 7;
            cp16(aBase + row * 144 + c * 16, g_wqh + (o0 + row) * CC + k0 + c * 8);
        }
        for (int u = tid; u < 1024; u += 256) {
            const int row = u >> 3, c = u & 7;
            cp16(bBase + row * 144 + c * 16,
                 g_xT + (size_t)(b * NPAD + n0 + row) * CC + k0 + c * 8);
        }
        asm volatile("cp.async.commit_group;" ::: "memory");
        asm volatile("cp.async.wait_group 0;" ::: "memory");
        __syncthreads();

#pragma unroll
        for (int kk = 0; kk < 4; ++kk) {
            uint32_t a[2][4];
#pragma unroll
            for (int mi = 0; mi < 2; ++mi) {
                const int r = wm * 32 + mi * 16;
                a[mi][0] = A32[(r + g) * 36 + kk * 8 + t];
                a[mi][1] = A32[(r + 8 + g) * 36 + kk * 8 + t];
                a[mi][2] = A32[(r + g) * 36 + kk * 8 + 4 + t];
                a[mi][3] = A32[(r + 8 + g) * 36 + kk * 8 + 4 + t];
            }
#pragma unroll
            for (int nj = 0; nj < 8; ++nj) {
                const uint32_t b0 = B32[(wn * 64 + nj * 8 + g) * 36 + kk * 8 + t];
                const uint32_t b1 = B32[(wn * 64 + nj * 8 + g) * 36 + kk * 8 + 4 + t];
#pragma unroll
                for (int mi = 0; mi < 2; ++mi)
                    mma_f16(C[mi][nj][0], C[mi][nj][1], C[mi][nj][2], C[mi][nj][3],
                            a[mi][0], a[mi][1], a[mi][2], a[mi][3], b0, b1);
            }
        }
        __syncthreads();
    }

#pragma unroll
    for (int mi = 0; mi < 2; ++mi) {
#pragma unroll
        for (int rh = 0; rh < 2; ++rh) {
            const int o   = o0 + wm * 32 + mi * 16 + rh * 8 + g;
            const int grp = o >> 7;
            const int rem = o & 127;
            const int h   = rem >> 5;
            const int d   = rem & 31;
            const int bh  = b * HEADS + h;
#pragma unroll
            for (int nj = 0; nj < 8; ++nj) {
                const int n = n0 + wn * 64 + nj * 8 + 2 * t;
                const float c0 = C[mi][nj][rh * 2 + 0];
                const float c1 = C[mi][nj][rh * 2 + 1];
                if (grp == 0) {
                    g_Qh[(size_t)(bh * NPAD + n) * DH + d]     = __float2half(c0 * SCALEF);
                    g_Qh[(size_t)(bh * NPAD + n + 1) * DH + d] = __float2half(c1 * SCALEF);
                } else if (grp == 1) {
                    g_K[(size_t)(bh * NPAD + n) * DH + d]     = __float2half(c0);
                    g_K[(size_t)(bh * NPAD + n + 1) * DH + d] = __float2half(c1);
                } else {
                    *(uint32_t*)&g_VT[((size_t)bh * DH + d) * NPAD + n] = pk2(c0, c1);
                }
            }
        }
    }
}

// ---------------------------------------------------------------------------
// Kernel 2: fp16 flash attention, QT=128 (16 queries/warp -> 512 fine-grained
// blocks for wave balance). 4-stage cp.async pipeline, 1 sync/tile.
// QK fp16-accum (C-frag feeds exp directly), PV fp32-accum, no-max softmax.
// ---------------------------------------------------------------------------
#define QT   128
#define KT   64
#define NST  4
#define SKW  20
#define SVW  36

__global__ __launch_bounds__(256) void flash_attn() {
    __shared__ uint32_t sK[NST * KT * SKW];
    __shared__ uint32_t sVT[NST * DH * SVW];

    const int bh = blockIdx.y, tid = threadIdx.x;
    const int warp = tid >> 5, lane = tid & 31;
    const int g = lane >> 2, t = lane & 3;

    const __half* gq = g_Qh + ((size_t)bh * NPAD + blockIdx.x * QT) * DH;
    const __half* gk = g_K + (size_t)bh * NPAD * DH;
    const __half* gvt = g_VT + (size_t)bh * DH * NPAD;

    // Q A-fragments (single m16 row block: rows warp*16 + {g, g+8})
    uint32_t qa[2][4];
    {
        const int r0 = warp * 16 + g;
#pragma unroll
        for (int ks = 0; ks < 2; ++ks) {
            const __half* q0 = gq + (size_t)r0 * DH + ks * 16;
            const __half* q8 = gq + (size_t)(r0 + 8) * DH + ks * 16;
            qa[ks][0] = *(const uint32_t*)(q0 + 2 * t);
            qa[ks][1] = *(const uint32_t*)(q8 + 2 * t);
            qa[ks][2] = *(const uint32_t*)(q0 + 8 + 2 * t);
            qa[ks][3] = *(const uint32_t*)(q8 + 8 + 2 * t);
        }
    }

    const uint32_t kbase = (uint32_t)__cvta_generic_to_shared(sK);
    const uint32_t vbase = (uint32_t)__cvta_generic_to_shared(sVT);

    auto prefetch = [&](int tile) {
        const int buf = tile & (NST - 1);
        const int jt  = tile * KT;
        const uint32_t kb = kbase + buf * KT * SKW * 4;
        const uint32_t vb = vbase + buf * DH * SVW * 4;
        for (int u = tid; u < 512; u += 256) {
            if (u < 256) {
                const int j = u >> 2, c = u & 3;
                cp16(kb + (j * SKW + c * 4) * 4, gk + (size_t)(jt + j) * DH + c * 8);
            } else {
                const int v = u - 256;
                const int d = v >> 3, c = v & 7;
                cp16(vb + (d * SVW + c * 4) * 4, gvt + (size_t)d * NPAD + jt + c * 8);
            }
        }
        asm volatile("cp.async.commit_group;" ::: "memory");
    };

    prefetch(0);
    prefetch(1);
    prefetch(2);

    float O[4][4] = {};
    float l0 = 0.f, l1 = 0.f;

    for (int tile = 0; tile < 65; ++tile) {
        if (tile < 63)       asm volatile("cp.async.wait_group 2;" ::: "memory");
        else if (tile == 63) asm volatile("cp.async.wait_group 1;" ::: "memory");
        else                 asm volatile("cp.async.wait_group 0;" ::: "memory");
        __syncthreads();

        const int buf = tile & (NST - 1);
        const uint32_t* bK = sK + buf * KT * SKW;
        const uint32_t* bV = sVT + buf * DH * SVW;
        const bool maskTile = (tile == 64);

        __half2 acc0 = __float2half2_rn(0.f), acc1 = acc0;
#pragma unroll
        for (int kp = 0; kp < 4; ++kp) {   // key pair-groups: nt = 2kp, 2kp+1
            uint32_t Pa[2], Pb[2];
#pragma unroll
            for (int h = 0; h < 2; ++h) {
                const int nt = 2 * kp + h;
                const uint32_t* krow = bK + (nt * 8 + g) * SKW;
                uint32_t sa = 0u, sb = 0u;
                mma_f16acc(sa, sb, qa[0][0], qa[0][1], qa[0][2], qa[0][3],
                           krow[t], krow[t + 4]);
                mma_f16acc(sa, sb, qa[1][0], qa[1][1], qa[1][2], qa[1][3],
                           krow[8 + t], krow[8 + t + 4]);
                uint32_t pa = h2exp2(sa);   // row g,   keys nt*8+2t,+1
                uint32_t pb = h2exp2(sb);   // row g+8
                if (maskTile && nt >= 2) { pa = pb = 0u; }
                Pa[h] = pa; Pb[h] = pb;
                acc0 = __hadd2(acc0, *(__half2*)&pa);
                acc1 = __hadd2(acc1, *(__half2*)&pb);
            }
            // PV for keys kp*16 .. kp*16+15
#pragma unroll
            for (int dt = 0; dt < 4; ++dt) {
                const uint32_t* vrow = bV + (dt * 8 + g) * SVW;
                mma_f16(O[dt][0], O[dt][1], O[dt][2], O[dt][3],
                        Pa[0], Pb[0], Pa[1], Pb[1],
                        vrow[kp * 8 + t], vrow[kp * 8 + t + 4]);
            }
        }
        {
            float2 f;
            f = __half22float2(acc0); l0 += f.x + f.y;
            f = __half22float2(acc1); l1 += f.x + f.y;
        }

        if (tile + 3 <= 64) prefetch(tile + 3);
    }

    // epilogue: quad-reduce l across t, normalize, store fp16 OT
    l0 += __shfl_xor_sync(0xffffffffu, l0, 1);
    l0 += __shfl_xor_sync(0xffffffffu, l0, 2);
    l1 += __shfl_xor_sync(0xffffffffu, l1, 1);
    l1 += __shfl_xor_sync(0xffffffffu, l1, 2);
    const float i0 = 1.f / l0, i1 = 1.f / l1;
    const int b = bh >> 2, h = bh & 3;
    const int r0 = blockIdx.x * QT + warp * 16 + g;
#pragma unroll
    for (int dt = 0; dt < 4; ++dt) {
        const int col = h * DH + dt * 8 + 2 * t;
        *(uint32_t*)&g_OT[(size_t)(b * HW + r0) * CC + col]     = pk2(O[dt][0] * i0, O[dt][1] * i0);
        *(uint32_t*)&g_OT[(size_t)(b * HW + r0 + 8) * CC + col] = pk2(O[dt][2] * i1, O[dt][3] * i1);
    }
}

// ---------------------------------------------------------------------------
// Kernel 3: out tensor-core GEMM. y[o][n] = sum_c w_out[o][c]*OT[n][c] + bias.
// ---------------------------------------------------------------------------
__global__ __launch_bounds__(256) void out_tc(const float* __restrict__ bias,
                                              float* __restrict__ y) {
    __shared__ __align__(16) __half sA[128 * 72];
    __shared__ __align__(16) __half sB[64 * 72];
    const int b  = blockIdx.y;
    const int n0 = blockIdx.x * 64;
    const int tid = threadIdx.x;
    const int warp = tid >> 5, lane = tid & 31;
    const int wm = warp >> 1, wn = warp & 1;
    const int g = lane >> 2, t = lane & 3;

    const uint32_t aBase = (uint32_t)__cvta_generic_to_shared(sA);
    const uint32_t bBase = (uint32_t)__cvta_generic_to_shared(sB);
    const uint32_t* A32 = (const uint32_t*)sA;
    const uint32_t* B32 = (const uint32_t*)sB;

    float C[2][4][4];
#pragma unroll
    for (int mi = 0; mi < 2; ++mi)
#pragma unroll
        for (int nj = 0; nj < 4; ++nj)
            C[mi][nj][0] = C[mi][nj][1] = C[mi][nj][2] = C[mi][nj][3] = 0.f;

    for (int kc = 0; kc < 2; ++kc) {
        const int k0 = kc * 64;
        for (int u = tid; u < 1024; u += 256) {
            const int row = u >> 3, c = u & 7;
            cp16(aBase + row * 144 + c * 16, g_woh + row * CC + k0 + c * 8);
        }
        for (int u = tid; u < 512; u += 256) {
            const int row = u >> 3, c = u & 7;
            cp16(bBase + row * 144 + c * 16,
                 g_OT + (size_t)(b * HW + n0 + row) * CC + k0 + c * 8);
        }
        asm volatile("cp.async.commit_group;" ::: "memory");
        asm volatile("cp.async.wait_group 0;" ::: "memory");
        __syncthreads();

#pragma unroll
        for (int kk = 0; kk < 4; ++kk) {
            uint32_t a[2][4];
#pragma unroll
            for (int mi = 0; mi < 2; ++mi) {
                const int r = wm * 32 + mi * 16;
                a[mi][0] = A32[(r + g) * 36 + kk * 8 + t];
                a[mi][1] = A32[(r + 8 + g) * 36 + kk * 8 + t];
                a[mi][2] = A32[(r + g) * 36 + kk * 8 + 4 + t];
                a[mi][3] = A32[(r + 8 + g) * 36 + kk * 8 + 4 + t];
            }
#pragma unroll
            for (int nj = 0; nj < 4; ++nj) {
                const uint32_t b0 = B32[(wn * 32 + nj * 8 + g) * 36 + kk * 8 + t];
                const uint32_t b1 = B32[(wn * 32 + nj * 8 + g) * 36 + kk * 8 + 4 + t];
#pragma unroll
                for (int mi = 0; mi < 2; ++mi)
                    mma_f16(C[mi][nj][0], C[mi][nj][1], C[mi][nj][2], C[mi][nj][3],
                            a[mi][0], a[mi][1], a[mi][2], a[mi][3], b0, b1);
            }
        }
        __syncthreads();
    }

#pragma unroll
    for (int mi = 0; mi < 2; ++mi) {
#pragma unroll
        for (int rh = 0; rh < 2; ++rh) {
            const int o = wm * 32 + mi * 16 + rh * 8 + g;
            const float bv = bias[o];
#pragma unroll
            for (int nj = 0; nj < 4; ++nj) {
                const int n = n0 + wn * 32 + nj * 8 + 2 * t;
                float2 r;
                r.x = C[mi][nj][rh * 2 + 0] + bv;
                r.y = C[mi][nj][rh * 2 + 1] + bv;
                *(float2*)&y[((size_t)b * CC + o) * HW + n] = r;
            }
        }
    }
}

// ---------------------------------------------------------------------------
extern "C" void kernel_launch(void* const* d_in, const int* in_sizes, int n_in,
                              void* d_out, int out_size) {
    const float* x     = (const float*)d_in[0];
    const float* memv  = (const float*)d_in[1];
    const float* w_qkv = (const float*)d_in[2];
    const float* w_out = (const float*)d_in[3];
    const float* b_out = (const float*)d_in[4];
    float* y = (float*)d_out;

    prep<<<456, 256>>>(x, memv, w_qkv, w_out);
    qkv_tc<<<dim3(NPAD / 128, 3, BB), 256>>>();
    flash_attn<<<dim3(HW / QT, NBH), 256>>>();      // 32 x 16 = 512 blocks
    out_tc<<<dim3(HW / 64, BB), 256>>>(b_out, y);
}

// round 16
// speedup vs baseline: 1.1418x; 1.1418x over previous
#include <cuda_runtime.h>
#include <cuda_fp16.h>
#include <cstdint>

#define BB    4
#define CC    128
#define HEADS 4
#define DH    32
#define HW    4096
#define MEMN  16
#define NTOT  4112   // HW + MEM
#define NPAD  4224   // 33*128, zero-padded tail
#define NBH   (BB * HEADS)

#define SCALEF 0.2550889456012103f  // rsqrt(32) * log2(e)

// scratch
__device__ __half g_xT[(size_t)BB * NPAD * CC];    // fp16 [b][n][c]
__device__ __half g_wqh[384 * CC];                 // fp16 w_qkv [o][c]
__device__ __half g_woh[CC * CC];                  // fp16 w_out [o][c]
__device__ __half g_Qh[(size_t)NBH * NPAD * DH];   // fp16 [bh][n][d], pre-scaled
__device__ __half g_K[(size_t)NBH * NPAD * DH];    // fp16 [bh][n][d]
__device__ __half g_VT[(size_t)NBH * DH * NPAD];   // fp16 [bh][d][n]
__device__ __half g_OT[(size_t)BB * HW * CC];      // fp16 [b][n][hid]

__device__ __forceinline__ uint32_t pk2(float lo, float hi) {
    __half2 h = __floats2half2_rn(lo, hi);
    return *(uint32_t*)&h;
}
__device__ __forceinline__ void mma_f16(float& d0, float& d1, float& d2, float& d3,
                                        uint32_t a0, uint32_t a1, uint32_t a2, uint32_t a3,
                                        uint32_t b0, uint32_t b1) {
    asm volatile("mma.sync.aligned.m16n8k16.row.col.f32.f16.f16.f32 "
                 "{%0,%1,%2,%3},{%4,%5,%6,%7},{%8,%9},{%0,%1,%2,%3};"
                 : "+f"(d0), "+f"(d1), "+f"(d2), "+f"(d3)
                 : "r"(a0), "r"(a1), "r"(a2), "r"(a3), "r"(b0), "r"(b1));
}
__device__ __forceinline__ void mma_f16acc(uint32_t& d0, uint32_t& d1,
                                           uint32_t a0, uint32_t a1, uint32_t a2, uint32_t a3,
                                           uint32_t b0, uint32_t b1) {
    asm volatile("mma.sync.aligned.m16n8k16.row.col.f16.f16.f16.f16 "
                 "{%0,%1},{%2,%3,%4,%5},{%6,%7},{%0,%1};"
                 : "+r"(d0), "+r"(d1)
                 : "r"(a0), "r"(a1), "r"(a2), "r"(a3), "r"(b0), "r"(b1));
}
__device__ __forceinline__ void cp16(uint32_t dst, const void* src) {
    asm volatile("cp.async.cg.shared.global [%0], [%1], 16;" :: "r"(dst), "l"(src));
}
__device__ __forceinline__ uint32_t h2exp2(uint32_t v) {
    uint32_t r;
    asm("ex2.approx.f16x2 %0, %1;" : "=r"(r) : "r"(v));
    return r;
}
__device__ __forceinline__ void ldsm4(uint32_t& r0, uint32_t& r1, uint32_t& r2, uint32_t& r3,
                                      uint32_t addr) {
    asm volatile("ldmatrix.sync.aligned.m8n8.x4.shared.b16 {%0,%1,%2,%3}, [%4];"
                 : "=r"(r0), "=r"(r1), "=r"(r2), "=r"(r3) : "r"(addr));
}

// ---------------------------------------------------------------------------
// Kernel 0: prep — weights->fp16 + x_ext->fp16 transposed, one launch.
// ---------------------------------------------------------------------------
__global__ __launch_bounds__(256) void prep(const float* __restrict__ x,
                                            const float* __restrict__ memv,
                                            const float* __restrict__ wq,
                                            const float* __restrict__ wo) {
    __shared__ __half s[64 * 136];
    const int tid = threadIdx.x;
    if (blockIdx.x < 264) {
        const int b = blockIdx.x / 66, n0 = (blockIdx.x % 66) * 64;
        for (int u = tid; u < 64 * CC; u += 256) {
            const int ci = u >> 6, nj = u & 63;
            const int n = n0 + nj;
            float v = 0.f;
            if (n < HW)        v = x[((size_t)b * CC + ci) * HW + n];
            else if (n < NTOT) v = memv[ci * MEMN + (n - HW)];
            s[nj * 136 + ci] = __float2half(v);
        }
        __syncthreads();
        for (int u = tid; u < 64 * 64; u += 256) {
            const int nj = u >> 6, w = u & 63;
            const int n = n0 + nj;
            if (n < NTOT)
                ((uint32_t*)&g_xT[(size_t)(b * NPAD + n) * CC])[w] = *(uint32_t*)&s[nj * 136 + w * 2];
        }
    } else {
        const int i = (blockIdx.x - 264) * 256 + tid;
        if (i < 384 * CC) g_wqh[i] = __float2half(wq[i]);
        if (i < CC * CC)  g_woh[i] = __float2half(wo[i]);
    }
}

// ---------------------------------------------------------------------------
// Kernel 1: qkv tensor-core GEMM. C[o][n] = sum_c w[o][c] * xT[n][c].
// ---------------------------------------------------------------------------
__global__ __launch_bounds__(256) void qkv_tc() {
    __shared__ __align__(16) __half sA[128 * 72];
    __shared__ __align__(16) __half sB[128 * 72];
    const int b  = blockIdx.z;
    const int o0 = blockIdx.y * 128;
    const int n0 = blockIdx.x * 128;
    const int tid = threadIdx.x;
    const int warp = tid >> 5, lane = tid & 31;
    const int wm = warp >> 1, wn = warp & 1;
    const int g = lane >> 2, t = lane & 3;

    const uint32_t aBase = (uint32_t)__cvta_generic_to_shared(sA);
    const uint32_t bBase = (uint32_t)__cvta_generic_to_shared(sB);
    const uint32_t* A32 = (const uint32_t*)sA;
    const uint32_t* B32 = (const uint32_t*)sB;

    float C[2][8][4];
#pragma unroll
    for (int mi = 0; mi < 2; ++mi)
#pragma unroll
        for (int nj = 0; nj < 8; ++nj)
            C[mi][nj][0] = C[mi][nj][1] = C[mi][nj][2] = C[mi][nj][3] = 0.f;

    for (int kc = 0; kc < 2; ++kc) {
        const int k0 = kc * 64;
        for (int u = tid; u < 1024; u += 256) {
            const int row = u >> 3, c = u & 7;
            cp16(aBase + row * 144 + c * 16, g_wqh + (o0 + row) * CC + k0 + c * 8);
        }
        for (int u = tid; u < 1024; u += 256) {
            const int row = u >> 3, c = u & 7;
            cp16(bBase + row * 144 + c * 16,
                 g_xT + (size_t)(b * NPAD + n0 + row) * CC + k0 + c * 8);
        }
        asm volatile("cp.async.commit_group;" ::: "memory");
        asm volatile("cp.async.wait_group 0;" ::: "memory");
        __syncthreads();

#pragma unroll
        for (int kk = 0; kk < 4; ++kk) {
            uint32_t a[2][4];
#pragma unroll
            for (int mi = 0; mi < 2; ++mi) {
                const int r = wm * 32 + mi * 16;
                a[mi][0] = A32[(r + g) * 36 + kk * 8 + t];
                a[mi][1] = A32[(r + 8 + g) * 36 + kk * 8 + t];
                a[mi][2] = A32[(r + g) * 36 + kk * 8 + 4 + t];
                a[mi][3] = A32[(r + 8 + g) * 36 + kk * 8 + 4 + t];
            }
#pragma unroll
            for (int nj = 0; nj < 8; ++nj) {
                const uint32_t b0 = B32[(wn * 64 + nj * 8 + g) * 36 + kk * 8 + t];
                const uint32_t b1 = B32[(wn * 64 + nj * 8 + g) * 36 + kk * 8 + 4 + t];
#pragma unroll
                for (int mi = 0; mi < 2; ++mi)
                    mma_f16(C[mi][nj][0], C[mi][nj][1], C[mi][nj][2], C[mi][nj][3],
                            a[mi][0], a[mi][1], a[mi][2], a[mi][3], b0, b1);
            }
        }
        __syncthreads();
    }

#pragma unroll
    for (int mi = 0; mi < 2; ++mi) {
#pragma unroll
        for (int rh = 0; rh < 2; ++rh) {
            const int o   = o0 + wm * 32 + mi * 16 + rh * 8 + g;
            const int grp = o >> 7;
            const int rem = o & 127;
            const int h   = rem >> 5;
            const int d   = rem & 31;
            const int bh  = b * HEADS + h;
#pragma unroll
            for (int nj = 0; nj < 8; ++nj) {
                const int n = n0 + wn * 64 + nj * 8 + 2 * t;
                const float c0 = C[mi][nj][rh * 2 + 0];
                const float c1 = C[mi][nj][rh * 2 + 1];
                if (grp == 0) {
                    g_Qh[(size_t)(bh * NPAD + n) * DH + d]     = __float2half(c0 * SCALEF);
                    g_Qh[(size_t)(bh * NPAD + n + 1) * DH + d] = __float2half(c1 * SCALEF);
                } else if (grp == 1) {
                    g_K[(size_t)(bh * NPAD + n) * DH + d]     = __float2half(c0);
                    g_K[(size_t)(bh * NPAD + n + 1) * DH + d] = __float2half(c1);
                } else {
                    *(uint32_t*)&g_VT[((size_t)bh * DH + d) * NPAD + n] = pk2(c0, c1);
                }
            }
        }
    }
}

// ---------------------------------------------------------------------------
// Kernel 2: fp16 flash attention (R13 structure) with ldmatrix.x4 K/V loads.
// QT=256, KT=64, 4-stage cp.async, 1 sync/tile. QK fp16-accum, PV fp32-accum.
// ---------------------------------------------------------------------------
#define QT   256
#define KT   64
#define NST  4
#define SKW  20
#define SVW  36

__global__ __launch_bounds__(256, 2) void flash_attn() {
    __shared__ uint32_t sK[NST * KT * SKW];
    __shared__ uint32_t sVT[NST * DH * SVW];

    const int bh = blockIdx.y, tid = threadIdx.x;
    const int warp = tid >> 5, lane = tid & 31;
    const int g = lane >> 2, t = lane & 3;

    const __half* gq = g_Qh + ((size_t)bh * NPAD + blockIdx.x * QT) * DH;
    const __half* gk = g_K + (size_t)bh * NPAD * DH;
    const __half* gvt = g_VT + (size_t)bh * DH * NPAD;

    uint32_t qa[2][2][4];
#pragma unroll
    for (int blk = 0; blk < 2; ++blk) {
        const int r0 = warp * 32 + blk * 16 + g;
#pragma unroll
        for (int ks = 0; ks < 2; ++ks) {
            const __half* q0 = gq + (size_t)r0 * DH + ks * 16;
            const __half* q8 = gq + (size_t)(r0 + 8) * DH + ks * 16;
            qa[blk][ks][0] = *(const uint32_t*)(q0 + 2 * t);
            qa[blk][ks][1] = *(const uint32_t*)(q8 + 2 * t);
            qa[blk][ks][2] = *(const uint32_t*)(q0 + 8 + 2 * t);
            qa[blk][ks][3] = *(const uint32_t*)(q8 + 8 + 2 * t);
        }
    }

    const uint32_t kbase = (uint32_t)__cvta_generic_to_shared(sK);
    const uint32_t vbase = (uint32_t)__cvta_generic_to_shared(sVT);

    // ldmatrix lane offsets (loop-invariant).
    // K (rows = keys, stride SKW): mat m = lane>>3 selects d-chunk m*4 words;
    // row j = lane&7.  -> r0=b00(d0:8) r1=b01(d8:16) r2=b10(d16:24) r3=b11(d24:32)
    const uint32_t kOff = (((uint32_t)(lane & 7)) * SKW + ((uint32_t)(lane >> 3)) * 4) * 4;
    // V (rows = d, stride SVW): mats = (dt octet lo/hi) x (key half 0/4 words);
    // lanes 0-7: d j, kh0; 8-15: d j, kh1; 16-23: d 8+j, kh0; 24-31: d 8+j, kh1
    const uint32_t vOff = ((((lane >> 4) ? 8u : 0u) + (uint32_t)(lane & 7)) * SVW
                           + (((uint32_t)(lane >> 3)) & 1u) * 4) * 4;

    auto prefetch = [&](int tile) {
        const int buf = tile & (NST - 1);
        const int jt  = tile * KT;
        const uint32_t kb = kbase + buf * KT * SKW * 4;
        const uint32_t vb = vbase + buf * DH * SVW * 4;
        for (int u = tid; u < 512; u += 256) {
            if (u < 256) {
                const int j = u >> 2, c = u & 3;
                cp16(kb + (j * SKW + c * 4) * 4, gk + (size_t)(jt + j) * DH + c * 8);
            } else {
                const int v = u - 256;
                const int d = v >> 3, c = v & 7;
                cp16(vb + (d * SVW + c * 4) * 4, gvt + (size_t)d * NPAD + jt + c * 8);
            }
        }
        asm volatile("cp.async.commit_group;" ::: "memory");
    };

    prefetch(0);
    prefetch(1);
    prefetch(2);

    float O0[4][4] = {}, O1[4][4] = {};
    float l00 = 0.f, l01 = 0.f, l10 = 0.f, l11 = 0.f;

    for (int tile = 0; tile < 65; ++tile) {
        if (tile < 63)       asm volatile("cp.async.wait_group 2;" ::: "memory");
        else if (tile == 63) asm volatile("cp.async.wait_group 1;" ::: "memory");
        else                 asm volatile("cp.async.wait_group 0;" ::: "memory");
        __syncthreads();

        const int buf = tile & (NST - 1);
        const uint32_t kb = kbase + buf * KT * SKW * 4 + kOff;
        const uint32_t vb = vbase + buf * DH * SVW * 4 + vOff;
        const bool maskTile = (tile == 64);

        // ---- S = Q K^T (fp16-accum); K B-frags via one ldmatrix.x4 per nt
        uint32_t P0a[8], P0b[8], P1a[8], P1b[8];
        __half2 a00 = __float2half2_rn(0.f), a01 = a00, a10 = a00, a11 = a00;
#pragma unroll
        for (int nt = 0; nt < 8; ++nt) {
            uint32_t b00, b01, b10, b11;
            ldsm4(b00, b01, b10, b11, kb + nt * (8 * SKW * 4));
            uint32_t s0a = 0u, s0b = 0u, s1a = 0u, s1b = 0u;
            mma_f16acc(s0a, s0b, qa[0][0][0], qa[0][0][1], qa[0][0][2], qa[0][0][3], b00, b01);
            mma_f16acc(s0a, s0b, qa[0][1][0], qa[0][1][1], qa[0][1][2], qa[0][1][3], b10, b11);
            mma_f16acc(s1a, s1b, qa[1][0][0], qa[1][0][1], qa[1][0][2], qa[1][0][3], b00, b01);
            mma_f16acc(s1a, s1b, qa[1][1][0], qa[1][1][1], qa[1][1][2], qa[1][1][3], b10, b11);
            uint32_t p0a = h2exp2(s0a);
            uint32_t p0b = h2exp2(s0b);
            uint32_t p1a = h2exp2(s1a);
            uint32_t p1b = h2exp2(s1b);
            if (maskTile && nt >= 2) { p0a = p0b = p1a = p1b = 0u; }
            P0a[nt] = p0a; P0b[nt] = p0b; P1a[nt] = p1a; P1b[nt] = p1b;
            a00 = __hadd2(a00, *(__half2*)&p0a);
            a01 = __hadd2(a01, *(__half2*)&p0b);
            a10 = __hadd2(a10, *(__half2*)&p1a);
            a11 = __hadd2(a11, *(__half2*)&p1b);
        }
        {
            float2 f;
            f = __half22float2(a00); l00 += f.x + f.y;
            f = __half22float2(a01); l01 += f.x + f.y;
            f = __half22float2(a10); l10 += f.x + f.y;
            f = __half22float2(a11); l11 += f.x + f.y;
        }

        // ---- O += P V; V B-frags via two ldmatrix.x4 per kp (keys kp*16..+15)
#pragma unroll
        for (int ks = 0; ks < 4; ++ks) {
            uint32_t v00, v01, v10, v11, v20, v21, v30, v31;
            ldsm4(v00, v01, v10, v11, vb + ks * 32);                      // dt 0,1
            ldsm4(v20, v21, v30, v31, vb + ks * 32 + 16 * SVW * 4);      // dt 2,3
            const uint32_t vb0[4] = {v00, v10, v20, v30};
            const uint32_t vb1[4] = {v01, v11, v21, v31};
#pragma unroll
            for (int dt = 0; dt < 4; ++dt) {
                mma_f16(O0[dt][0], O0[dt][1], O0[dt][2], O0[dt][3],
                        P0a[2 * ks], P0b[2 * ks], P0a[2 * ks + 1], P0b[2 * ks + 1],
                        vb0[dt], vb1[dt]);
                mma_f16(O1[dt][0], O1[dt][1], O1[dt][2], O1[dt][3],
                        P1a[2 * ks], P1b[2 * ks], P1a[2 * ks + 1], P1b[2 * ks + 1],
                        vb0[dt], vb1[dt]);
            }
        }

        if (tile + 3 <= 64) prefetch(tile + 3);
    }

    l00 += __shfl_xor_sync(0xffffffffu, l00, 1);
    l00 += __shfl_xor_sync(0xffffffffu, l00, 2);
    l01 += __shfl_xor_sync(0xffffffffu, l01, 1);
    l01 += __shfl_xor_sync(0xffffffffu, l01, 2);
    l10 += __shfl_xor_sync(0xffffffffu, l10, 1);
    l10 += __shfl_xor_sync(0xffffffffu, l10, 2);
    l11 += __shfl_xor_sync(0xffffffffu, l11, 1);
    l11 += __shfl_xor_sync(0xffffffffu, l11, 2);
    const float i00 = 1.f / l00, i01 = 1.f / l01;
    const float i10 = 1.f / l10, i11 = 1.f / l11;
    const int b = bh >> 2, h = bh & 3;
    const int r0 = blockIdx.x * QT + warp * 32 + g;
#pragma unroll
    for (int dt = 0; dt < 4; ++dt) {
        const int col = h * DH + dt * 8 + 2 * t;
        *(uint32_t*)&g_OT[(size_t)(b * HW + r0) * CC + col]      = pk2(O0[dt][0] * i00, O0[dt][1] * i00);
        *(uint32_t*)&g_OT[(size_t)(b * HW + r0 + 8) * CC + col]  = pk2(O0[dt][2] * i01, O0[dt][3] * i01);
        *(uint32_t*)&g_OT[(size_t)(b * HW + r0 + 16) * CC + col] = pk2(O1[dt][0] * i10, O1[dt][1] * i10);
        *(uint32_t*)&g_OT[(size_t)(b * HW + r0 + 24) * CC + col] = pk2(O1[dt][2] * i11, O1[dt][3] * i11);
    }
}

// ---------------------------------------------------------------------------
// Kernel 3: out tensor-core GEMM. y[o][n] = sum_c w_out[o][c]*OT[n][c] + bias.
// ---------------------------------------------------------------------------
__global__ __launch_bounds__(256) void out_tc(const float* __restrict__ bias,
                                              float* __restrict__ y) {
    __shared__ __align__(16) __half sA[128 * 72];
    __shared__ __align__(16) __half sB[64 * 72];
    const int b  = blockIdx.y;
    const int n0 = blockIdx.x * 64;
    const int tid = threadIdx.x;
    const int warp = tid >> 5, lane = tid & 31;
    const int wm = warp >> 1, wn = warp & 1;
    const int g = lane >> 2, t = lane & 3;

    const uint32_t aBase = (uint32_t)__cvta_generic_to_shared(sA);
    const uint32_t bBase = (uint32_t)__cvta_generic_to_shared(sB);
    const uint32_t* A32 = (const uint32_t*)sA;
    const uint32_t* B32 = (const uint32_t*)sB;

    float C[2][4][4];
#pragma unroll
    for (int mi = 0; mi < 2; ++mi)
#pragma unroll
        for (int nj = 0; nj < 4; ++nj)
            C[mi][nj][0] = C[mi][nj][1] = C[mi][nj][2] = C[mi][nj][3] = 0.f;

    for (int kc = 0; kc < 2; ++kc) {
        const int k0 = kc * 64;
        for (int u = tid; u < 1024; u += 256) {
            const int row = u >> 3, c = u & 7;
            cp16(aBase + row * 144 + c * 16, g_woh + row * CC + k0 + c * 8);
        }
        for (int u = tid; u < 512; u += 256) {
            const int row = u >> 3, c = u & 7;
            cp16(bBase + row * 144 + c * 16,
                 g_OT + (size_t)(b * HW + n0 + row) * CC + k0 + c * 8);
        }
        asm volatile("cp.async.commit_group;" ::: "memory");
        asm volatile("cp.async.wait_group 0;" ::: "memory");
        __syncthreads();

#pragma unroll
        for (int kk = 0; kk < 4; ++kk) {
            uint32_t a[2][4];
#pragma unroll
            for (int mi = 0; mi < 2; ++mi) {
                const int r = wm * 32 + mi * 16;
                a[mi][0] = A32[(r + g) * 36 + kk * 8 + t];
                a[mi][1] = A32[(r + 8 + g) * 36 + kk * 8 + t];
                a[mi][2] = A32[(r + g) * 36 + kk * 8 + 4 + t];
                a[mi][3] = A32[(r + 8 + g) * 36 + kk * 8 + 4 + t];
            }
#pragma unroll
            for (int nj = 0; nj < 4; ++nj) {
                const uint32_t b0 = B32[(wn * 32 + nj * 8 + g) * 36 + kk * 8 + t];
                const uint32_t b1 = B32[(wn * 32 + nj * 8 + g) * 36 + kk * 8 + 4 + t];
#pragma unroll
                for (int mi = 0; mi < 2; ++mi)
                    mma_f16(C[mi][nj][0], C[mi][nj][1], C[mi][nj][2], C[mi][nj][3],
                            a[mi][0], a[mi][1], a[mi][2], a[mi][3], b0, b1);
            }
        }
        __syncthreads();
    }

#pragma unroll
    for (int mi = 0; mi < 2; ++mi) {
#pragma unroll
        for (int rh = 0; rh < 2; ++rh) {
            const int o = wm * 32 + mi * 16 + rh * 8 + g;
            const float bv = bias[o];
#pragma unroll
            for (int nj = 0; nj < 4; ++nj) {
                const int n = n0 + wn * 32 + nj * 8 + 2 * t;
                float2 r;
                r.x = C[mi][nj][rh * 2 + 0] + bv;
                r.y = C[mi][nj][rh * 2 + 1] + bv;
                *(float2*)&y[((size_t)b * CC + o) * HW + n] = r;
            }
        }
    }
}

// ---------------------------------------------------------------------------
extern "C" void kernel_launch(void* const* d_in, const int* in_sizes, int n_in,
                              void* d_out, int out_size) {
    const float* x     = (const float*)d_in[0];
    const float* memv  = (const float*)d_in[1];
    const float* w_qkv = (const float*)d_in[2];
    const float* w_out = (const float*)d_in[3];
    const float* b_out = (const float*)d_in[4];
    float* y = (float*)d_out;

    prep<<<456, 256>>>(x, memv, w_qkv, w_out);
    qkv_tc<<<dim3(NPAD / 128, 3, BB), 256>>>();
    flash_attn<<<dim3(HW / QT, NBH), 256>>>();      // 16 x 16 = 256 blocks
    out_tc<<<dim3(HW / 64, BB), 256>>>(b_out, y);
}